// round 3
// baseline (speedup 1.0000x reference)
#include <cuda_runtime.h>
#include <cstdint>
#include <cstddef>

#define NX  256
#define NU  32
#define NY  32
#define BB  16
#define TT  8192
#define LCH 128
#define NC  64    // TT / LCH

// -------- scratch (allocation-free: __device__ globals; total ~0.5 MB) --------
__device__ float g_BzT[NU * NX];          // [u][n]  = (Q^T Bmat)^T
__device__ float g_CzT[NX * NY];          // [n][y]  = (C Q)^T
__device__ float g_DT [NU * NY];          // [u][y]
__device__ float g_z0 [BB * NX];          // x0 @ Q
__device__ float g_w  [BB * NC * NX];     // per-chunk Horner sums
__device__ float g_ss [BB * NC * NX];     // chunk-start states

// -------- prep: Bz, Cz, z0, D^T --------
__global__ __launch_bounds__(256) void prep_kernel(
    const float* __restrict__ x0, const float* __restrict__ Q,
    const float* __restrict__ Bmat, const float* __restrict__ C,
    const float* __restrict__ D)
{
    int idx = blockIdx.x * 256 + threadIdx.x;
    if (idx < NU * NX) {                              // BzT[u][n]
        int u = idx >> 8, n = idx & 255;
        float a = 0.f;
        for (int i = 0; i < NX; i++) a = fmaf(Q[i * NX + n], Bmat[i * NU + u], a);
        g_BzT[u * NX + n] = a;
    } else if (idx < NU * NX + NY * NX) {             // CzT[n][y]
        int j = idx - NU * NX;
        int y = j >> 8, n = j & 255;
        float a = 0.f;
        for (int i = 0; i < NX; i++) a = fmaf(C[y * NX + i], Q[i * NX + n], a);
        g_CzT[n * NY + y] = a;
    } else if (idx < NU * NX + NY * NX + BB * NX) {   // z0[b][n]
        int j = idx - NU * NX - NY * NX;
        int b = j >> 8, n = j & 255;
        float a = 0.f;
        for (int i = 0; i < NX; i++) a = fmaf(x0[b * NX + i], Q[i * NX + n], a);
        g_z0[b * NX + n] = a;
    } else if (idx < NU * NX + NY * NX + BB * NX + NU * NY) {  // DT[u][y]
        int j = idx - NU * NX - NY * NX - BB * NX;
        int u = j >> 5, y = j & 31;
        g_DT[u * NY + y] = D[y * NU + u];
    }
}

// -------- pass1: per-chunk Horner sum w_c = sum_j lam^{L-1-j} (Bz u_j) --------
__global__ __launch_bounds__(256) void pass1_kernel(
    const float* __restrict__ u, const float* __restrict__ lam)
{
    int b = blockIdx.x >> 6;          // / NC
    int c = blockIdx.x & (NC - 1);
    int n = threadIdx.x;

    __shared__ float s_u[LCH * NU];   // 16 KB chunk of u

    const float4* up4 = (const float4*)(u + ((size_t)b * TT + (size_t)c * LCH) * NU);
    float4* su4 = (float4*)s_u;
    #pragma unroll
    for (int i = 0; i < (LCH * NU / 4) / 256; i++)
        su4[n + i * 256] = up4[n + i * 256];

    float bz[NU];                     // Bz row for mode n, in registers
    #pragma unroll
    for (int k = 0; k < NU; k++) bz[k] = g_BzT[k * NX + n];
    float lamn = lam[n];
    __syncthreads();

    float w = 0.f;
    for (int j = 0; j < LCH; j++) {
        const float4* uu = (const float4*)(s_u + j * NU);
        float v0 = 0.f, v1 = 0.f, v2 = 0.f, v3 = 0.f;
        #pragma unroll
        for (int k4 = 0; k4 < 8; k4++) {
            float4 q = uu[k4];                 // broadcast LDS.128
            v0 = fmaf(bz[4 * k4 + 0], q.x, v0);
            v1 = fmaf(bz[4 * k4 + 1], q.y, v1);
            v2 = fmaf(bz[4 * k4 + 2], q.z, v2);
            v3 = fmaf(bz[4 * k4 + 3], q.w, v3);
        }
        float v = (v0 + v1) + (v2 + v3);
        w = fmaf(lamn, w, v);                  // Horner
    }
    g_w[((size_t)b * NC + c) * NX + n] = w;
}

// -------- chunkscan: states at chunk boundaries --------
__global__ __launch_bounds__(256) void chunkscan_kernel(const float* __restrict__ lam)
{
    int b = blockIdx.x;
    int n = threadIdx.x;
    float lamL = lam[n];
    #pragma unroll
    for (int i = 0; i < 7; i++) lamL *= lamL;   // lam^128
    float s = g_z0[b * NX + n];
    for (int c = 0; c < NC; c++) {
        size_t o = ((size_t)b * NC + c) * NX + n;
        g_ss[o] = s;
        s = fmaf(lamL, s, g_w[o]);
    }
}

// -------- pass3: local scan (v recomputed) + y = Cz s + D u --------
__global__ __launch_bounds__(256) void pass3_kernel(
    const float* __restrict__ u, const float* __restrict__ lam,
    float* __restrict__ y)
{
    int b   = blockIdx.x >> 6;
    int c   = blockIdx.x & (NC - 1);
    int tid = threadIdx.x;
    int w   = tid >> 5;     // warp id: owns modes [32w, 32w+32)
    int l   = tid & 31;     // lane: owns output y = l for this warp's modes

    __shared__ float s_s[NX];          // state s_t
    __shared__ float s_part[NX];       // partials [warp][lane]
    __shared__ float s_u[LCH * NU];    // 16 KB chunk of u
    __shared__ float s_dt[NU * NY];    // D^T

    const float4* up4 = (const float4*)(u + ((size_t)b * TT + (size_t)c * LCH) * NU);
    float4* su4 = (float4*)s_u;
    #pragma unroll
    for (int i = 0; i < 4; i++) su4[tid + i * 256] = up4[tid + i * 256];
    #pragma unroll
    for (int i = 0; i < 4; i++) {
        int j = tid + i * 256;
        if (j < NU * NY) s_dt[j] = g_DT[j];
    }

    float bz[NU];                      // Bz row for mode tid
    #pragma unroll
    for (int k = 0; k < NU; k++) bz[k] = g_BzT[k * NX + tid];
    float cz[32];                      // Cz[l][32w + k] (conflict-free)
    #pragma unroll
    for (int k = 0; k < 32; k++) cz[k] = g_CzT[(w * 32 + k) * NY + l];
    float lamn = lam[tid];
    s_s[tid] = g_ss[((size_t)b * NC + c) * NX + tid];
    __syncthreads();

    float* yp = y + ((size_t)b * TT + (size_t)c * LCH) * NY;

    for (int j = 0; j < LCH; j++) {
        const float4* uu = (const float4*)(s_u + j * NU);

        // v_t for this thread's mode: 32 FMA against broadcast u row
        float v0 = 0.f, v1 = 0.f, v2 = 0.f, v3 = 0.f;
        #pragma unroll
        for (int k4 = 0; k4 < 8; k4++) {
            float4 q = uu[k4];
            v0 = fmaf(bz[4 * k4 + 0], q.x, v0);
            v1 = fmaf(bz[4 * k4 + 1], q.y, v1);
            v2 = fmaf(bz[4 * k4 + 2], q.z, v2);
            v3 = fmaf(bz[4 * k4 + 3], q.w, v3);
        }
        float v = (v0 + v1) + (v2 + v3);

        // partial y_t: this warp's 32 modes vs output l (uses state BEFORE update)
        float p0 = 0.f, p1 = 0.f, p2 = 0.f, p3 = 0.f;
        const float4* ss = (const float4*)(s_s + w * 32);
        #pragma unroll
        for (int k4 = 0; k4 < 8; k4++) {
            float4 sv = ss[k4];
            p0 = fmaf(cz[4 * k4 + 0], sv.x, p0);
            p1 = fmaf(cz[4 * k4 + 1], sv.y, p1);
            p2 = fmaf(cz[4 * k4 + 2], sv.z, p2);
            p3 = fmaf(cz[4 * k4 + 3], sv.w, p3);
        }
        float snew = fmaf(lamn, s_s[tid], v);   // s_{t+1} = lam s_t + v_t
        s_part[tid] = (p0 + p1) + (p2 + p3);
        __syncthreads();
        s_s[tid] = snew;

        if (tid < NY) {                // final reduce + D u + store
            float acc = 0.f;
            #pragma unroll
            for (int ww = 0; ww < 8; ww++) acc += s_part[ww * 32 + tid];
            const float* ur = s_u + j * NU;
            #pragma unroll
            for (int k = 0; k < NU; k++) acc = fmaf(s_dt[k * NY + tid], ur[k], acc);
            yp[(size_t)j * NY + tid] = acc;
        }
        __syncthreads();
    }
}

// -------- launch --------
extern "C" void kernel_launch(void* const* d_in, const int* in_sizes, int n_in,
                              void* d_out, int out_size)
{
    const float* x0   = (const float*)d_in[0];
    const float* u    = (const float*)d_in[1];
    const float* Q    = (const float*)d_in[2];
    const float* lam  = (const float*)d_in[3];
    const float* Bmat = (const float*)d_in[4];
    const float* C    = (const float*)d_in[5];
    const float* D    = (const float*)d_in[6];
    float* y = (float*)d_out;
    (void)in_sizes; (void)n_in; (void)out_size;

    prep_kernel<<<84, 256>>>(x0, Q, Bmat, C, D);
    pass1_kernel<<<BB * NC, 256>>>(u, lam);
    chunkscan_kernel<<<BB, 256>>>(lam);
    pass3_kernel<<<BB * NC, 256>>>(u, lam, y);
}

// round 4
// speedup vs baseline: 1.5924x; 1.5924x over previous
#include <cuda_runtime.h>
#include <cstdint>
#include <cstddef>

#define NX  256
#define NU  32
#define NY  32
#define BB  16
#define TT  8192
#define LCH 128
#define NC  64    // TT / LCH
#define KG  8     // steps per reduction group in pass3

// -------- scratch (allocation-free: __device__ globals) --------
__device__ float g_BzT[NU * NX];          // [u][n]  = (Q^T Bmat)^T
__device__ float g_CzT[NX * NY];          // [n][y]  = (C Q)^T
__device__ float g_DT [NU * NY];          // [u][y]
__device__ float g_z0 [BB * NX];          // x0 @ Q
__device__ float g_w  [BB * NC * NX];     // per-chunk Horner sums
__device__ float g_ss [BB * NC * NX];     // chunk-start states
__device__ float g_v  [(size_t)BB * TT * NX];   // v_t = Bz u_t  (128 MB)

// -------- prep: Bz, Cz, z0, D^T --------
__global__ __launch_bounds__(256) void prep_kernel(
    const float* __restrict__ x0, const float* __restrict__ Q,
    const float* __restrict__ Bmat, const float* __restrict__ C,
    const float* __restrict__ D)
{
    int idx = blockIdx.x * 256 + threadIdx.x;
    if (idx < NU * NX) {                              // BzT[u][n]
        int u = idx >> 8, n = idx & 255;
        float a = 0.f;
        for (int i = 0; i < NX; i++) a = fmaf(Q[i * NX + n], Bmat[i * NU + u], a);
        g_BzT[u * NX + n] = a;
    } else if (idx < NU * NX + NY * NX) {             // CzT[n][y]
        int j = idx - NU * NX;
        int y = j >> 8, n = j & 255;
        float a = 0.f;
        for (int i = 0; i < NX; i++) a = fmaf(C[y * NX + i], Q[i * NX + n], a);
        g_CzT[n * NY + y] = a;
    } else if (idx < NU * NX + NY * NX + BB * NX) {   // z0[b][n]
        int j = idx - NU * NX - NY * NX;
        int b = j >> 8, n = j & 255;
        float a = 0.f;
        for (int i = 0; i < NX; i++) a = fmaf(x0[b * NX + i], Q[i * NX + n], a);
        g_z0[b * NX + n] = a;
    } else if (idx < NU * NX + NY * NX + BB * NX + NU * NY) {  // DT[u][y]
        int j = idx - NU * NX - NY * NX - BB * NX;
        int u = j >> 5, y = j & 31;
        g_DT[u * NY + y] = D[y * NU + u];
    }
}

// -------- pass1: v_t = Bz u_t (stored) + per-chunk Horner sum w_c --------
__global__ __launch_bounds__(256) void pass1_kernel(
    const float* __restrict__ u, const float* __restrict__ lam)
{
    int b = blockIdx.x >> 6;          // / NC
    int c = blockIdx.x & (NC - 1);
    int n = threadIdx.x;

    __shared__ float s_u[LCH * NU];   // 16 KB chunk of u

    const float4* up4 = (const float4*)(u + ((size_t)b * TT + (size_t)c * LCH) * NU);
    float4* su4 = (float4*)s_u;
    #pragma unroll
    for (int i = 0; i < (LCH * NU / 4) / 256; i++)
        su4[n + i * 256] = up4[n + i * 256];

    float bz[NU];                     // Bz row for mode n, in registers
    #pragma unroll
    for (int k = 0; k < NU; k++) bz[k] = g_BzT[k * NX + n];
    float lamn = lam[n];
    __syncthreads();

    float w = 0.f;
    float* vout = g_v + ((size_t)b * TT + (size_t)c * LCH) * NX + n;
    for (int j = 0; j < LCH; j++) {
        const float4* uu = (const float4*)(s_u + j * NU);
        float v0 = 0.f, v1 = 0.f, v2 = 0.f, v3 = 0.f;
        #pragma unroll
        for (int k4 = 0; k4 < 8; k4++) {
            float4 q = uu[k4];                 // broadcast LDS.128
            v0 = fmaf(bz[4 * k4 + 0], q.x, v0);
            v1 = fmaf(bz[4 * k4 + 1], q.y, v1);
            v2 = fmaf(bz[4 * k4 + 2], q.z, v2);
            v3 = fmaf(bz[4 * k4 + 3], q.w, v3);
        }
        float v = (v0 + v1) + (v2 + v3);
        w = fmaf(lamn, w, v);                  // Horner
        vout[(size_t)j * NX] = v;              // coalesced 1KB/block/step
    }
    g_w[((size_t)b * NC + c) * NX + n] = w;
}

// -------- chunkscan: states at chunk boundaries --------
__global__ __launch_bounds__(256) void chunkscan_kernel(const float* __restrict__ lam)
{
    int b = blockIdx.x;
    int n = threadIdx.x;
    float lamL = lam[n];
    #pragma unroll
    for (int i = 0; i < 7; i++) lamL *= lamL;   // lam^128
    float s = g_z0[b * NX + n];
    for (int c = 0; c < NC; c++) {
        size_t o = ((size_t)b * NC + c) * NX + n;
        g_ss[o] = s;
        s = fmaf(lamL, s, g_w[o]);
    }
}

// -------- pass3: warp-autonomous scan + batched y reduction --------
__global__ __launch_bounds__(256) void pass3_kernel(
    const float* __restrict__ u, const float* __restrict__ lam,
    float* __restrict__ y)
{
    int b   = blockIdx.x >> 6;
    int c   = blockIdx.x & (NC - 1);
    int tid = threadIdx.x;
    int w   = tid >> 5;     // warp id: owns modes [32w, 32w+32)
    int l   = tid & 31;     // lane: partial for output y=l over this warp's modes

    __shared__ float s_u[LCH * NU];        // 16 KB chunk of u (for D*u)
    __shared__ float s_dt[NU * NY];        // 4 KB D^T
    __shared__ float s_part[KG * NX];      // 8 KB partials [step][warp*32+l]
    __shared__ float s_st[2][NX];          // 2 KB state ping-pong

    const float4* up4 = (const float4*)(u + ((size_t)b * TT + (size_t)c * LCH) * NU);
    float4* su4 = (float4*)s_u;
    #pragma unroll
    for (int i = 0; i < 4; i++) su4[tid + i * 256] = up4[tid + i * 256];
    #pragma unroll
    for (int i = 0; i < 4; i++) {
        int j = tid + i * 256;
        if (j < NU * NY) s_dt[j] = g_DT[j];
    }

    float cz[32];                          // Cz[l][32w + k] (conflict-free load)
    #pragma unroll
    for (int k = 0; k < 32; k++) cz[k] = g_CzT[(w * 32 + k) * NY + l];
    float lamn = lam[tid];
    float smy = g_ss[((size_t)b * NC + c) * NX + tid];   // my mode's state
    s_st[0][tid] = smy;
    __syncthreads();

    const float* vp = g_v + ((size_t)b * TT + (size_t)c * LCH) * NX + tid;
    float* yp = y + ((size_t)b * TT + (size_t)c * LCH) * NY;

    int jj_red = tid >> 5;                 // reduce phase: this thread's step
    int yy_red = tid & 31;                 //               and output index

    for (int g = 0; g < LCH / KG; g++) {
        int j0 = g * KG;

        // prefetch this group's v values (MLP=8, coalesced)
        float vb[KG];
        #pragma unroll
        for (int jj = 0; jj < KG; jj++)
            vb[jj] = vp[(size_t)(j0 + jj) * NX];

        // 8 scan steps, warp-local, no block barrier
        #pragma unroll
        for (int jj = 0; jj < KG; jj++) {
            int pb = jj & 1;
            // partial y: this warp's 32 modes (pre-update state) vs output l
            const float4* ss = (const float4*)(s_st[pb] + w * 32);
            float p0 = 0.f, p1 = 0.f, p2 = 0.f, p3 = 0.f;
            #pragma unroll
            for (int k4 = 0; k4 < 8; k4++) {
                float4 sv = ss[k4];
                p0 = fmaf(cz[4 * k4 + 0], sv.x, p0);
                p1 = fmaf(cz[4 * k4 + 1], sv.y, p1);
                p2 = fmaf(cz[4 * k4 + 2], sv.z, p2);
                p3 = fmaf(cz[4 * k4 + 3], sv.w, p3);
            }
            s_part[jj * NX + tid] = (p0 + p1) + (p2 + p3);
            smy = fmaf(lamn, smy, vb[jj]);          // state update (register)
            s_st[pb ^ 1][tid] = smy;                // publish to warp-mates
            __syncwarp();
        }

        __syncthreads();
        // reduce: thread (jj_red, yy_red) sums 8 warps + D*u, writes y row
        {
            float acc = 0.f;
            #pragma unroll
            for (int ww = 0; ww < 8; ww++)
                acc += s_part[jj_red * NX + ww * 32 + yy_red];
            const float* ur = s_u + (j0 + jj_red) * NU;
            #pragma unroll
            for (int k = 0; k < NU; k++)
                acc = fmaf(s_dt[k * NY + yy_red], ur[k], acc);
            yp[(size_t)(j0 + jj_red) * NY + yy_red] = acc;
        }
        __syncthreads();
    }
}

// -------- launch --------
extern "C" void kernel_launch(void* const* d_in, const int* in_sizes, int n_in,
                              void* d_out, int out_size)
{
    const float* x0   = (const float*)d_in[0];
    const float* u    = (const float*)d_in[1];
    const float* Q    = (const float*)d_in[2];
    const float* lam  = (const float*)d_in[3];
    const float* Bmat = (const float*)d_in[4];
    const float* C    = (const float*)d_in[5];
    const float* D    = (const float*)d_in[6];
    float* y = (float*)d_out;
    (void)in_sizes; (void)n_in; (void)out_size;

    prep_kernel<<<84, 256>>>(x0, Q, Bmat, C, D);
    pass1_kernel<<<BB * NC, 256>>>(u, lam);
    chunkscan_kernel<<<BB, 256>>>(lam);
    pass3_kernel<<<BB * NC, 256>>>(u, lam, y);
}

// round 5
// speedup vs baseline: 1.7193x; 1.0797x over previous
#include <cuda_runtime.h>
#include <cstdint>
#include <cstddef>

#define NX  256
#define NU  32
#define NY  32
#define BB  16
#define TT  8192
#define LCH 128
#define NC  64    // TT / LCH
#define KG  8     // steps per group in pass3
#define NG  (LCH / KG)   // 16 groups

// -------- scratch (allocation-free: __device__ globals) --------
__device__ float g_BzT[NU * NX];          // [u][n]  = (Q^T Bmat)^T
__device__ float g_CzT[NX * NY];          // [n][y]  = (C Q)^T
__device__ float g_DT [NU * NY];          // [u][y]
__device__ float g_z0 [BB * NX];          // x0 @ Q
__device__ float g_w  [BB * NC * NX];     // per-chunk Horner sums
__device__ float g_ss [BB * NC * NX];     // chunk-start states
__device__ float g_v  [(size_t)BB * TT * NX];   // v_t = Bz u_t  (128 MB)

__device__ __forceinline__ uint32_t smem_u32(const void* p) {
    uint32_t a;
    asm("{ .reg .u64 t; cvta.to.shared.u64 t, %1; cvt.u32.u64 %0, t; }" : "=r"(a) : "l"(p));
    return a;
}
__device__ __forceinline__ void cp_async16(uint32_t saddr, const void* gptr) {
    asm volatile("cp.async.cg.shared.global [%0], [%1], 16;" :: "r"(saddr), "l"(gptr));
}
__device__ __forceinline__ void cp_commit() {
    asm volatile("cp.async.commit_group;");
}
template <int N> __device__ __forceinline__ void cp_wait() {
    asm volatile("cp.async.wait_group %0;" :: "n"(N));
}

// -------- prep: Bz, Cz, z0, D^T --------
__global__ __launch_bounds__(256) void prep_kernel(
    const float* __restrict__ x0, const float* __restrict__ Q,
    const float* __restrict__ Bmat, const float* __restrict__ C,
    const float* __restrict__ D)
{
    int idx = blockIdx.x * 256 + threadIdx.x;
    if (idx < NU * NX) {                              // BzT[u][n]
        int u = idx >> 8, n = idx & 255;
        float a = 0.f;
        #pragma unroll 8
        for (int i = 0; i < NX; i++) a = fmaf(Q[i * NX + n], Bmat[i * NU + u], a);
        g_BzT[u * NX + n] = a;
    } else if (idx < NU * NX + NY * NX) {             // CzT[n][y]
        int j = idx - NU * NX;
        int y = j >> 8, n = j & 255;
        float a = 0.f;
        #pragma unroll 8
        for (int i = 0; i < NX; i++) a = fmaf(C[y * NX + i], Q[i * NX + n], a);
        g_CzT[n * NY + y] = a;
    } else if (idx < NU * NX + NY * NX + BB * NX) {   // z0[b][n]
        int j = idx - NU * NX - NY * NX;
        int b = j >> 8, n = j & 255;
        float a = 0.f;
        #pragma unroll 8
        for (int i = 0; i < NX; i++) a = fmaf(x0[b * NX + i], Q[i * NX + n], a);
        g_z0[b * NX + n] = a;
    } else if (idx < NU * NX + NY * NX + BB * NX + NU * NY) {  // DT[u][y]
        int j = idx - NU * NX - NY * NX - BB * NX;
        int u = j >> 5, y = j & 31;
        g_DT[u * NY + y] = D[y * NU + u];
    }
}

// -------- pass1: v_t = Bz u_t (stored) + per-chunk Horner sum w_c --------
__global__ __launch_bounds__(256) void pass1_kernel(
    const float* __restrict__ u, const float* __restrict__ lam)
{
    int b = blockIdx.x >> 6;          // / NC
    int c = blockIdx.x & (NC - 1);
    int n = threadIdx.x;

    __shared__ float s_u[LCH * NU];   // 16 KB chunk of u

    const float4* up4 = (const float4*)(u + ((size_t)b * TT + (size_t)c * LCH) * NU);
    float4* su4 = (float4*)s_u;
    #pragma unroll
    for (int i = 0; i < (LCH * NU / 4) / 256; i++)
        su4[n + i * 256] = up4[n + i * 256];

    float bz[NU];                     // Bz row for mode n, in registers
    #pragma unroll
    for (int k = 0; k < NU; k++) bz[k] = g_BzT[k * NX + n];
    float lamn = lam[n];
    __syncthreads();

    float w = 0.f;
    float* vout = g_v + ((size_t)b * TT + (size_t)c * LCH) * NX + n;
    #pragma unroll 2
    for (int j = 0; j < LCH; j++) {
        const float4* uu = (const float4*)(s_u + j * NU);
        float v0 = 0.f, v1 = 0.f, v2 = 0.f, v3 = 0.f;
        #pragma unroll
        for (int k4 = 0; k4 < 8; k4++) {
            float4 q = uu[k4];                 // broadcast LDS.128
            v0 = fmaf(bz[4 * k4 + 0], q.x, v0);
            v1 = fmaf(bz[4 * k4 + 1], q.y, v1);
            v2 = fmaf(bz[4 * k4 + 2], q.z, v2);
            v3 = fmaf(bz[4 * k4 + 3], q.w, v3);
        }
        float v = (v0 + v1) + (v2 + v3);
        w = fmaf(lamn, w, v);                  // Horner
        vout[(size_t)j * NX] = v;              // coalesced
    }
    g_w[((size_t)b * NC + c) * NX + n] = w;
}

// -------- chunkscan: states at chunk boundaries (batched MLP) --------
__global__ __launch_bounds__(256) void chunkscan_kernel(const float* __restrict__ lam)
{
    int b = blockIdx.x;
    int n = threadIdx.x;
    float lamL = lam[n];
    #pragma unroll
    for (int i = 0; i < 7; i++) lamL *= lamL;   // lam^128
    float s = g_z0[b * NX + n];
    const size_t base = (size_t)b * NC * NX + n;
    for (int cg = 0; cg < NC / 16; cg++) {
        float wv[16];
        #pragma unroll
        for (int i = 0; i < 16; i++)            // MLP=16 batched loads
            wv[i] = g_w[base + (size_t)(cg * 16 + i) * NX];
        #pragma unroll
        for (int i = 0; i < 16; i++) {
            g_ss[base + (size_t)(cg * 16 + i) * NX] = s;
            s = fmaf(lamL, s, wv[i]);
        }
    }
}

// -------- pass3: warp-autonomous scan, cp.async v pipeline, batched reduce --------
__global__ __launch_bounds__(256) void pass3_kernel(
    const float* __restrict__ u, const float* __restrict__ lam,
    float* __restrict__ y)
{
    int b   = blockIdx.x >> 6;
    int c   = blockIdx.x & (NC - 1);
    int tid = threadIdx.x;
    int w   = tid >> 5;     // warp id: owns modes [32w, 32w+32)
    int l   = tid & 31;     // lane: partial for output y=l over this warp's modes

    __shared__ float s_u[LCH * NU];        // 16 KB chunk of u (for D*u)
    __shared__ float s_dt[NU * NY];        // 4 KB D^T
    __shared__ float s_part[2][KG * NX];   // 16 KB partials, double-buffered
    __shared__ float s_st[2][NX];          // 2 KB state ping-pong
    __shared__ float s_v[2][KG * NX];      // 16 KB v staging, double-buffered

    const float* vbase = g_v + ((size_t)b * TT + (size_t)c * LCH) * NX;

    // kick off v prefetch for group 0 immediately (2 x 16B per thread)
    {
        uint32_t dst = smem_u32(&s_v[0][0]) + tid * 16u;
        cp_async16(dst,        vbase + tid * 4);
        cp_async16(dst + 4096, vbase + 1024 + tid * 4);
        cp_commit();
    }

    const float4* up4 = (const float4*)(u + ((size_t)b * TT + (size_t)c * LCH) * NU);
    float4* su4 = (float4*)s_u;
    #pragma unroll
    for (int i = 0; i < 4; i++) su4[tid + i * 256] = up4[tid + i * 256];
    #pragma unroll
    for (int i = 0; i < 4; i++) {
        int j = tid + i * 256;
        if (j < NU * NY) s_dt[j] = g_DT[j];
    }

    float cz[32];                          // Cz[l][32w + k] (conflict-free load)
    #pragma unroll
    for (int k = 0; k < 32; k++) cz[k] = g_CzT[(w * 32 + k) * NY + l];
    float lamn = lam[tid];
    float smy = g_ss[((size_t)b * NC + c) * NX + tid];   // my mode's state
    s_st[0][tid] = smy;

    float* yp = y + ((size_t)b * TT + (size_t)c * LCH) * NY;
    int jj_red = tid >> 5;                 // reduce phase: this thread's step
    int yy_red = tid & 31;                 //               and output index

    cp_wait<0>();
    __syncthreads();                       // v(0) + s_u + s_dt + s_st visible

    for (int g = 0; g < NG; g++) {
        int gb = g & 1;

        // 8 scan steps, warp-local (reads s_v[gb], writes s_part[gb])
        #pragma unroll
        for (int jj = 0; jj < KG; jj++) {
            int pb = jj & 1;
            const float4* ss = (const float4*)(s_st[pb] + w * 32);
            float p0 = 0.f, p1 = 0.f, p2 = 0.f, p3 = 0.f;
            #pragma unroll
            for (int k4 = 0; k4 < 8; k4++) {
                float4 sv = ss[k4];
                p0 = fmaf(cz[4 * k4 + 0], sv.x, p0);
                p1 = fmaf(cz[4 * k4 + 1], sv.y, p1);
                p2 = fmaf(cz[4 * k4 + 2], sv.z, p2);
                p3 = fmaf(cz[4 * k4 + 3], sv.w, p3);
            }
            s_part[gb][jj * NX + tid] = (p0 + p1) + (p2 + p3);
            smy = fmaf(lamn, smy, s_v[gb][jj * NX + tid]);  // state update
            s_st[pb ^ 1][tid] = smy;                        // publish to warp
            __syncwarp();
        }

        // prefetch v(g+1) into the other buffer — overlaps barrier + reduce
        if (g + 1 < NG) {
            const float* src = vbase + (size_t)(g + 1) * KG * NX;
            uint32_t dst = smem_u32(&s_v[gb ^ 1][0]) + tid * 16u;
            cp_async16(dst,        src + tid * 4);
            cp_async16(dst + 4096, src + 1024 + tid * 4);
            cp_commit();
        }

        __syncthreads();                   // s_part(g) complete across warps

        // reduce: thread (jj_red, yy_red) sums 8 warps + D*u, writes y row
        {
            float acc = 0.f;
            #pragma unroll
            for (int ww = 0; ww < 8; ww++)
                acc += s_part[gb][jj_red * NX + ww * 32 + yy_red];
            const float* ur = s_u + (g * KG + jj_red) * NU;
            #pragma unroll
            for (int k = 0; k < NU; k++)
                acc = fmaf(s_dt[k * NY + yy_red], ur[k], acc);
            yp[(size_t)(g * KG + jj_red) * NY + yy_red] = acc;
        }

        cp_wait<0>();
        __syncthreads();                   // v(g+1) visible; s_part reuse safe
    }
}

// -------- launch --------
extern "C" void kernel_launch(void* const* d_in, const int* in_sizes, int n_in,
                              void* d_out, int out_size)
{
    const float* x0   = (const float*)d_in[0];
    const float* u    = (const float*)d_in[1];
    const float* Q    = (const float*)d_in[2];
    const float* lam  = (const float*)d_in[3];
    const float* Bmat = (const float*)d_in[4];
    const float* C    = (const float*)d_in[5];
    const float* D    = (const float*)d_in[6];
    float* y = (float*)d_out;
    (void)in_sizes; (void)n_in; (void)out_size;

    prep_kernel<<<84, 256>>>(x0, Q, Bmat, C, D);
    pass1_kernel<<<BB * NC, 256>>>(u, lam);
    chunkscan_kernel<<<BB, 256>>>(lam);
    pass3_kernel<<<BB * NC, 256>>>(u, lam, y);
}